// round 6
// baseline (speedup 1.0000x reference)
#include <cuda_runtime.h>
#include <cstdint>

#define T_LEN   512
#define BATCH   2048
#define NB      8            // batches per block; 2 blocks co-resident per SM
#define HID     64
#define NGATE   256
#define THREADS 256          // 8 warps: warp = 32-row slice x 8 batches
#define WP      68           // w_sh row stride: row r starts bank 4r mod 32
#define HP      68           // h_sh row stride
#define GP      264          // gbuf row stride (bank 8b + r: conflict-free)
#define XP      65           // x_sh row stride

typedef unsigned long long ull;

__device__ __forceinline__ uint32_t smem_u32(const void* p) {
    uint32_t a;
    asm("{ .reg .u64 t; cvta.to.shared.u64 t, %1; cvt.u32.u64 %0, t; }"
        : "=r"(a) : "l"(p));
    return a;
}
// 16B shared load straight into two b64 regs (no pack MOVs)
__device__ __forceinline__ void lds_v2u64(ull& a, ull& b, uint32_t addr) {
    asm volatile("ld.shared.v2.u64 {%0, %1}, [%2];"
                 : "=l"(a), "=l"(b) : "r"(addr));
}
__device__ __forceinline__ ull pack2(float x, float y) {
    ull r; asm("mov.b64 %0, {%1, %2};" : "=l"(r) : "f"(x), "f"(y)); return r;
}
__device__ __forceinline__ void unpack2(ull v, float& x, float& y) {
    asm("mov.b64 {%0, %1}, %2;" : "=f"(x), "=f"(y) : "l"(v));
}
// Packed f32x2 FMA (sm_10x FFMA2) — IEEE fp32 per lane, 2x FFMA throughput.
__device__ __forceinline__ ull fma2(ull a, ull b, ull c) {
    ull d; asm("fma.rn.f32x2 %0, %1, %2, %3;" : "=l"(d) : "l"(a), "l"(b), "l"(c));
    return d;
}
// MUFU tanh (validated in R5: rel_err ~1e-6 end-to-end)
__device__ __forceinline__ float tanh_mufu(float x) {
    float r; asm("tanh.approx.f32 %0, %1;" : "=f"(r) : "f"(x)); return r;
}
// sigmoid(x) = 0.5*tanh(0.5x) + 0.5  (1 MUFU)
__device__ __forceinline__ float sigm(float x) {
    return fmaf(tanh_mufu(0.5f * x), 0.5f, 0.5f);
}

__global__ __launch_bounds__(THREADS, 2)
void lstm_kernel(const float* __restrict__ x,
                 const float* __restrict__ w_ih,
                 const float* __restrict__ w_hh,
                 const float* __restrict__ b_ih,
                 const float* __restrict__ b_hh,
                 const float* __restrict__ w_fc,
                 const float* __restrict__ b_fc,
                 float* __restrict__ out)
{
    extern __shared__ float smem[];
    float* w_sh = smem;                       // [NGATE][WP]  69632 B
    float* h_sh = w_sh + NGATE * WP;          // [NB][HP]      2176 B
    float* gbuf = h_sh + NB * HP;             // [NB][GP]      8448 B
    float* x_sh = gbuf + NB * GP;             // [NB][XP]      2080 B
                                              // total ~82.4 KB -> 2 blocks/SM

    const int tid  = threadIdx.x;
    const int lane = tid & 31;
    const int warp = tid >> 5;                // 0..7: row slice warp*32..+31
    const int rg   = lane & 7;                // row offset within 8-group
    const int bl   = lane >> 3;               // batch lane group 0..3
    const int b0   = blockIdx.x * NB;

    // ---- stage w_hh into padded shared; zero h; stage x chunk 0 ----
    for (int idx = tid; idx < NGATE * HID; idx += THREADS) {
        int r = idx >> 6, k = idx & 63;
        w_sh[r * WP + k] = w_hh[idx];
    }
    for (int idx = tid; idx < NB * HP; idx += THREADS) h_sh[idx] = 0.0f;
    for (int idx = tid; idx < NB * HID; idx += THREADS) {
        int b = idx >> 6, t2 = idx & 63;
        x_sh[b * XP + t2] = x[(size_t)(b0 + b) * T_LEN + t2];
    }

    // ---- matvec identity: rows r_j = warp*32+rg+8j (j=0..3), batches bl+4i (i=0..1) ----
    float wih[4], bias[4];
    uint32_t waddr[4], haddr[2];
    const uint32_t wbase = smem_u32(w_sh);
    const uint32_t hbase = smem_u32(h_sh);
    #pragma unroll
    for (int j = 0; j < 4; ++j) {
        int r = warp * 32 + rg + 8 * j;
        wih[j]   = w_ih[r];                   // I == 1
        bias[j]  = b_ih[r] + b_hh[r];
        waddr[j] = wbase + (uint32_t)(r * WP) * 4u;
    }
    #pragma unroll
    for (int i = 0; i < 2; ++i)
        haddr[i] = hbase + (uint32_t)((bl + 4 * i) * HP) * 4u;

    // ---- update identity: warp = batch, units lane and lane+32 ----
    const float wfc0 = w_fc[lane], wfc1 = w_fc[lane + 32];
    float c0 = 0.0f, c1 = 0.0f;
    const float bfc = b_fc[0];

    __syncthreads();

    for (int t = 0; t < T_LEN; ++t) {
        const int tt = t & 63;

        // ---- matvec phase: acc[j][i] = gates(row j, batch i), f32x2 over k ----
        ull acc[4][2];
        #pragma unroll
        for (int i = 0; i < 2; ++i) {
            float xv = x_sh[(bl + 4 * i) * XP + tt];
            #pragma unroll
            for (int j = 0; j < 4; ++j)
                acc[j][i] = pack2(fmaf(xv, wih[j], bias[j]), 0.0f);
        }

        ull chlo[2], chhi[2], cwlo[4], cwhi[4];
        #pragma unroll
        for (int i = 0; i < 2; ++i) lds_v2u64(chlo[i], chhi[i], haddr[i]);
        #pragma unroll
        for (int j = 0; j < 4; ++j) lds_v2u64(cwlo[j], cwhi[j], waddr[j]);

        #pragma unroll
        for (int kc = 0; kc < 16; ++kc) {
            ull nhlo[2], nhhi[2], nwlo[4], nwhi[4];
            if (kc < 15) {                      // prefetch next chunk (compile-time)
                const uint32_t off = 16u * (uint32_t)(kc + 1);
                #pragma unroll
                for (int i = 0; i < 2; ++i) lds_v2u64(nhlo[i], nhhi[i], haddr[i] + off);
                #pragma unroll
                for (int j = 0; j < 4; ++j) lds_v2u64(nwlo[j], nwhi[j], waddr[j] + off);
            }
            #pragma unroll
            for (int j = 0; j < 4; ++j)
                #pragma unroll
                for (int i = 0; i < 2; ++i) {
                    acc[j][i] = fma2(chlo[i], cwlo[j], acc[j][i]);
                    acc[j][i] = fma2(chhi[i], cwhi[j], acc[j][i]);
                }
            if (kc < 15) {
                #pragma unroll
                for (int i = 0; i < 2; ++i) { chlo[i] = nhlo[i]; chhi[i] = nhhi[i]; }
                #pragma unroll
                for (int j = 0; j < 4; ++j) { cwlo[j] = nwlo[j]; cwhi[j] = nwhi[j]; }
            }
        }

        // gates -> gbuf (bank = 8*bl + rg (+8j const) : 32 distinct per STS)
        #pragma unroll
        for (int j = 0; j < 4; ++j) {
            int r = warp * 32 + rg + 8 * j;
            #pragma unroll
            for (int i = 0; i < 2; ++i) {
                float lo, hi; unpack2(acc[j][i], lo, hi);
                gbuf[(bl + 4 * i) * GP + r] = lo + hi;
            }
        }
        __syncthreads();                        // bar1: gates visible

        // ---- update phase: warp = batch `warp`, units lane & lane+32 ----
        // PyTorch gate order i,f,g,o at offsets 0,64,128,192
        const float* gb = gbuf + warp * GP;
        float gi0 = gb[lane],       gf0 = gb[lane + 64];
        float gg0 = gb[lane + 128], go0 = gb[lane + 192];
        float gi1 = gb[lane + 32],  gf1 = gb[lane + 96];
        float gg1 = gb[lane + 160], go1 = gb[lane + 224];

        float iv0 = sigm(gi0), fv0 = sigm(gf0);
        float gv0 = tanh_mufu(gg0), ov0 = sigm(go0);
        c0 = fmaf(fv0, c0, iv0 * gv0);
        float hv0 = ov0 * tanh_mufu(c0);

        float iv1 = sigm(gi1), fv1 = sigm(gf1);
        float gv1 = tanh_mufu(gg1), ov1 = sigm(go1);
        c1 = fmaf(fv1, c1, iv1 * gv1);
        float hv1 = ov1 * tanh_mufu(c1);

        h_sh[warp * HP + lane]      = hv0;
        h_sh[warp * HP + lane + 32] = hv1;

        // ---- output head: out[b][t] = h . w_fc + b_fc (full-warp reduce) ----
        float po = fmaf(hv0, wfc0, hv1 * wfc1);
        #pragma unroll
        for (int off = 16; off > 0; off >>= 1)
            po += __shfl_xor_sync(0xffffffffu, po, off);
        if (lane == 0) out[(size_t)(b0 + warp) * T_LEN + t] = po + bfc;

        // stage next x chunk (after bar1 so this chunk's reads are done)
        if (tt == 63 && t + 1 < T_LEN) {
            #pragma unroll
            for (int q = 0; q < 2; ++q) {
                int idx = tid + 256 * q;
                int b = idx >> 6, t2 = idx & 63;
                x_sh[b * XP + t2] = x[(size_t)(b0 + b) * T_LEN + (t + 1) + t2];
            }
        }
        __syncthreads();                        // bar2: h + x visible for next step
    }
}

extern "C" void kernel_launch(void* const* d_in, const int* in_sizes, int n_in,
                              void* d_out, int out_size)
{
    const float* x    = (const float*)d_in[0];
    const float* w_ih = (const float*)d_in[1];
    const float* w_hh = (const float*)d_in[2];
    const float* b_ih = (const float*)d_in[3];
    const float* b_hh = (const float*)d_in[4];
    const float* w_fc = (const float*)d_in[5];
    const float* b_fc = (const float*)d_in[6];
    float* out = (float*)d_out;

    size_t smem = (size_t)(NGATE * WP + NB * HP + NB * GP + NB * XP) * sizeof(float);
    cudaFuncSetAttribute(lstm_kernel,
                         cudaFuncAttributeMaxDynamicSharedMemorySize, (int)smem);
    lstm_kernel<<<BATCH / NB, THREADS, smem>>>(x, w_ih, w_hh, b_ih, b_hh,
                                               w_fc, b_fc, out);
}

// round 8
// speedup vs baseline: 1.6048x; 1.6048x over previous
#include <cuda_runtime.h>
#include <cuda_bf16.h>
#include <cstdint>

#define T_LEN   512
#define BATCH   2048
#define NB      16            // batches per CTA (= GEMM N)
#define HID     64
#define THREADS 256           // 8 warps; warp = 32 gate rows
#define HSTRIDE 44            // u32 words per batch row of H (bank-verified)
#define GP      260           // floats per batch row of gbuf (bank-verified)

static __device__ __forceinline__ float tanh_mufu(float x) {
    float r; asm("tanh.approx.f32 %0, %1;" : "=f"(r) : "f"(x)); return r;
}
static __device__ __forceinline__ float sigm(float x) {
    return fmaf(tanh_mufu(0.5f * x), 0.5f, 0.5f);
}
static __device__ __forceinline__ uint32_t pk2(__nv_bfloat16 a, __nv_bfloat16 b) {
    return ((uint32_t)__bfloat16_as_ushort(b) << 16) | (uint32_t)__bfloat16_as_ushort(a);
}
// split (a,b) into packed hi and lo bf16x2 words (low half = first element)
static __device__ __forceinline__ void split2(float a, float b,
                                              uint32_t& hi, uint32_t& lo) {
    __nv_bfloat16 ah = __float2bfloat16(a), bh = __float2bfloat16(b);
    __nv_bfloat16 al = __float2bfloat16(a - __bfloat162float(ah));
    __nv_bfloat16 bl = __float2bfloat16(b - __bfloat162float(bh));
    hi = pk2(ah, bh); lo = pk2(al, bl);
}

// Ampere-class HMMA: m16n8k16, A row-major bf16, B col-major bf16, f32 accum
#define MMA_BF16(d, a, b0v, b1v)                                              \
    asm volatile("mma.sync.aligned.m16n8k16.row.col.f32.bf16.bf16.f32 "        \
        "{%0,%1,%2,%3}, {%4,%5,%6,%7}, {%8,%9}, {%0,%1,%2,%3};"                \
        : "+f"((d)[0]), "+f"((d)[1]), "+f"((d)[2]), "+f"((d)[3])               \
        : "r"((a)[0]), "r"((a)[1]), "r"((a)[2]), "r"((a)[3]),                  \
          "r"(b0v), "r"(b1v))

__global__ __launch_bounds__(THREADS, 1)
void lstm_kernel(const float* __restrict__ x,
                 const float* __restrict__ w_ih,
                 const float* __restrict__ w_hh,
                 const float* __restrict__ b_ih,
                 const float* __restrict__ b_hh,
                 const float* __restrict__ w_fc,
                 const float* __restrict__ b_fc,
                 float* __restrict__ out)
{
    __shared__ uint32_t Hhi[NB * HSTRIDE];   // bf16x2 words: [b][k/2]
    __shared__ uint32_t Hlo[NB * HSTRIDE];
    __shared__ float    gbuf[NB * GP];       // [b][gate row]
    __shared__ float    x_sh[2][NB][64];
    __shared__ float    obuf[2][NB];

    const int tid  = threadIdx.x;
    const int lane = tid & 31;
    const int wid  = tid >> 5;
    const int qid  = lane >> 2;               // fragment groupID
    const int tig  = lane & 3;                // thread-in-group
    const int b0   = blockIdx.x * NB;

    // ---- build resident W_aug fragments (hi/lo split), rows = gate index ----
    // K layout: k<64 = w_hh, k=64 = w_ih (I==1), k=65 = b_ih+b_hh, else 0
    uint32_t whi[2][5][4], wlo[2][5][4];
    #pragma unroll
    for (int mt = 0; mt < 2; ++mt) {
        #pragma unroll
        for (int kt = 0; kt < 5; ++kt) {
            const int r0 = 32 * wid + 16 * mt + qid;
            const int k0 = 16 * kt + 2 * tig;
            #pragma unroll
            for (int rr = 0; rr < 4; ++rr) {          // a0..a3
                const int g = r0 + ((rr & 1) ? 8 : 0);
                const int k = k0 + ((rr & 2) ? 8 : 0);
                float v0 = 0.f, v1 = 0.f;
                #pragma unroll
                for (int e = 0; e < 2; ++e) {
                    const int kk = k + e;
                    float v = 0.f;
                    if (kk < 64)       v = w_hh[g * HID + kk];
                    else if (kk == 64) v = w_ih[g];
                    else if (kk == 65) v = b_ih[g] + b_hh[g];
                    if (e == 0) v0 = v; else v1 = v;
                }
                split2(v0, v1, whi[mt][kt][rr], wlo[mt][kt][rr]);
            }
        }
    }

    // ---- init H = 0; x chunk 0; k=64/65 slots for t=0 ----
    for (int i = tid; i < NB * HSTRIDE; i += THREADS) { Hhi[i] = 0u; Hlo[i] = 0u; }
    for (int i = tid; i < NB * 64; i += THREADS) {
        int b = i >> 6, s = i & 63;
        x_sh[0][b][s] = x[(size_t)(b0 + b) * T_LEN + s];
    }
    __syncthreads();
    if (tid < NB) {
        float xv = x_sh[0][tid][0];
        uint32_t hi, lo;
        split2(xv, 1.0f, hi, lo);
        lo &= 0xFFFFu;                         // bias lo = 0 exactly
        Hhi[tid * HSTRIDE + 32] = hi;
        Hlo[tid * HSTRIDE + 32] = lo;
    }

    // ---- update-phase identity: uu = unit, bg = batch group ----
    const int uu = tid & 63;
    const int bg = tid >> 6;
    const int half = wid & 1;
    const int rbg  = wid >> 1;
    const float wfc = w_fc[uu];
    const float bfc = b_fc[0];
    float c[4] = {0.f, 0.f, 0.f, 0.f};

    __syncthreads();

    for (int t = 0; t < T_LEN; ++t) {
        // ---- MMA phase: gates = Whi*Hhi + Whi*Hlo + Wlo*Hhi ----
        float acc[2][2][4];
        #pragma unroll
        for (int mt = 0; mt < 2; ++mt)
            #pragma unroll
            for (int nt = 0; nt < 2; ++nt)
                #pragma unroll
                for (int i = 0; i < 4; ++i) acc[mt][nt][i] = 0.f;

        #pragma unroll
        for (int kt = 0; kt < 5; ++kt) {
            uint32_t bh[2][2], bl[2][2];
            #pragma unroll
            for (int nt = 0; nt < 2; ++nt) {
                const int base = (8 * nt + qid) * HSTRIDE + 8 * kt + tig;
                bh[nt][0] = Hhi[base]; bh[nt][1] = Hhi[base + 4];
                bl[nt][0] = Hlo[base]; bl[nt][1] = Hlo[base + 4];
            }
            #pragma unroll
            for (int mt = 0; mt < 2; ++mt)
                #pragma unroll
                for (int nt = 0; nt < 2; ++nt) {
                    MMA_BF16(acc[mt][nt], whi[mt][kt], bh[nt][0], bh[nt][1]);
                    MMA_BF16(acc[mt][nt], whi[mt][kt], bl[nt][0], bl[nt][1]);
                    MMA_BF16(acc[mt][nt], wlo[mt][kt], bh[nt][0], bh[nt][1]);
                }
        }

        // ---- scatter c-frags to gbuf[b][g] (bank-verified conflict-free) ----
        #pragma unroll
        for (int mt = 0; mt < 2; ++mt)
            #pragma unroll
            for (int nt = 0; nt < 2; ++nt) {
                const int g = 32 * wid + 16 * mt + qid;
                const int b = 8 * nt + 2 * tig;
                gbuf[b * GP + g]           = acc[mt][nt][0];
                gbuf[(b + 1) * GP + g]     = acc[mt][nt][1];
                gbuf[b * GP + g + 8]       = acc[mt][nt][2];
                gbuf[(b + 1) * GP + g + 8] = acc[mt][nt][3];
            }
        __syncthreads();                        // bar1: gates visible

        // ---- update: thread (uu, batches bg+4j); PyTorch order i,f,g,o ----
        float po[4];
        #pragma unroll
        for (int j = 0; j < 4; ++j) {
            const int b = bg + 4 * j;
            const float* gb = gbuf + b * GP;
            float gi = gb[uu], gf = gb[64 + uu];
            float gg = gb[128 + uu], go = gb[192 + uu];
            float iv = sigm(gi), fv = sigm(gf);
            float gv = tanh_mufu(gg), ov = sigm(go);
            c[j] = fmaf(fv, c[j], iv * gv);
            float hv = ov * tanh_mufu(c[j]);
            po[j] = hv * wfc;
            __nv_bfloat16 hh = __float2bfloat16(hv);
            __nv_bfloat16 hl = __float2bfloat16(hv - __bfloat162float(hh));
            ((__nv_bfloat16*)Hhi)[b * (2 * HSTRIDE) + uu] = hh;
            ((__nv_bfloat16*)Hlo)[b * (2 * HSTRIDE) + uu] = hl;
        }

        // x/bias slot for step t+1
        if (tid < NB && t + 1 < T_LEN) {
            const int tn = t + 1;
            float xv = x_sh[(tn >> 6) & 1][tid][tn & 63];
            uint32_t hi, lo;
            split2(xv, 1.0f, hi, lo);
            lo &= 0xFFFFu;
            Hhi[tid * HSTRIDE + 32] = hi;
            Hlo[tid * HSTRIDE + 32] = lo;
        }
        // stage next 64-step x chunk at chunk start
        if ((t & 63) == 0 && (t >> 6) + 1 < T_LEN / 64) {
            const int nc = (t >> 6) + 1;
            #pragma unroll
            for (int q = 0; q < 4; ++q) {
                int idx = tid + THREADS * q;
                int b = idx >> 6, s = idx & 63;
                x_sh[nc & 1][b][s] = x[(size_t)(b0 + b) * T_LEN + nc * 64 + s];
            }
        }

        // ---- output head partials ----
        #pragma unroll
        for (int off = 16; off > 0; off >>= 1)
            #pragma unroll
            for (int j = 0; j < 4; ++j)
                po[j] += __shfl_xor_sync(0xffffffffu, po[j], off);
        if (lane == 0) {
            #pragma unroll
            for (int j = 0; j < 4; ++j)
                obuf[half][rbg + 4 * j] = po[j];
        }
        __syncthreads();                        // bar2: H + obuf visible

        if (tid < NB)
            out[(size_t)(b0 + tid) * T_LEN + t] =
                obuf[0][tid] + obuf[1][tid] + bfc;
    }
}

extern "C" void kernel_launch(void* const* d_in, const int* in_sizes, int n_in,
                              void* d_out, int out_size)
{
    const float* x    = (const float*)d_in[0];
    const float* w_ih = (const float*)d_in[1];
    const float* w_hh = (const float*)d_in[2];
    const float* b_ih = (const float*)d_in[3];
    const float* b_hh = (const float*)d_in[4];
    const float* w_fc = (const float*)d_in[5];
    const float* b_fc = (const float*)d_in[6];
    float* out = (float*)d_out;

    lstm_kernel<<<BATCH / NB, THREADS>>>(x, w_ih, w_hh, b_ih, b_hh,
                                         w_fc, b_fc, out);
}

// round 10
// speedup vs baseline: 2.6442x; 1.6477x over previous
#include <cuda_runtime.h>
#include <cuda_bf16.h>
#include <cstdint>

#define T_LEN   512
#define BATCH   2048
#define NB      16            // batches per CTA
#define HID     64
#define THREADS 512           // 16 warps: (w&7) = 32-row slice, (w>>3) = batch half
#define HSTRIDE 44            // u32 words per batch row of H (bank-verified)
#define GP      260           // floats per batch row of gbuf (bank-verified)

static __device__ __forceinline__ float tanh_mufu(float x) {
    float r; asm("tanh.approx.f32 %0, %1;" : "=f"(r) : "f"(x)); return r;
}
static __device__ __forceinline__ float sigm(float x) {
    return fmaf(tanh_mufu(0.5f * x), 0.5f, 0.5f);
}
static __device__ __forceinline__ uint32_t pk2(__nv_bfloat16 a, __nv_bfloat16 b) {
    return ((uint32_t)__bfloat16_as_ushort(b) << 16) | (uint32_t)__bfloat16_as_ushort(a);
}
// split (a,b) into packed hi and lo bf16x2 words (low half = first element)
static __device__ __forceinline__ void split2(float a, float b,
                                              uint32_t& hi, uint32_t& lo) {
    __nv_bfloat16 ah = __float2bfloat16(a), bh = __float2bfloat16(b);
    __nv_bfloat16 al = __float2bfloat16(a - __bfloat162float(ah));
    __nv_bfloat16 bl = __float2bfloat16(b - __bfloat162float(bh));
    hi = pk2(ah, bh); lo = pk2(al, bl);
}

// Ampere-class HMMA: m16n8k16, A row-major bf16, B col-major bf16, f32 accum
#define MMA_BF16(d, a, b0v, b1v)                                              \
    asm volatile("mma.sync.aligned.m16n8k16.row.col.f32.bf16.bf16.f32 "        \
        "{%0,%1,%2,%3}, {%4,%5,%6,%7}, {%8,%9}, {%0,%1,%2,%3};"                \
        : "+f"((d)[0]), "+f"((d)[1]), "+f"((d)[2]), "+f"((d)[3])               \
        : "r"((a)[0]), "r"((a)[1]), "r"((a)[2]), "r"((a)[3]),                  \
          "r"(b0v), "r"(b1v))

__global__ __launch_bounds__(THREADS, 1)
void lstm_kernel(const float* __restrict__ x,
                 const float* __restrict__ w_ih,
                 const float* __restrict__ w_hh,
                 const float* __restrict__ b_ih,
                 const float* __restrict__ b_hh,
                 const float* __restrict__ w_fc,
                 const float* __restrict__ b_fc,
                 float* __restrict__ out)
{
    __shared__ uint32_t Hhi[NB * HSTRIDE];   // bf16x2 words: [b][k/2]
    __shared__ uint32_t Hlo[NB * HSTRIDE];
    __shared__ float    gbuf[NB * GP];       // [b][gate row]
    __shared__ float    x_sh[2][NB][64];

    const int tid  = threadIdx.x;
    const int lane = tid & 31;
    const int wid  = tid >> 5;
    const int wrow = wid & 7;                 // row-slice warp id
    const int bh8  = wid >> 3;                // batch half (0: b 0-7, 1: b 8-15)
    const int qid  = lane >> 2;               // fragment groupID
    const int tig  = lane & 3;                // thread-in-group
    const int b0   = blockIdx.x * NB;

    // ---- build resident W_aug fragments (hi/lo split), rows = gate index ----
    // K layout: k<64 = w_hh, k=64 = w_ih (I==1), k=65 = b_ih+b_hh, else 0
    uint32_t whi[2][5][4], wlo[2][5][4];
    #pragma unroll
    for (int mt = 0; mt < 2; ++mt) {
        #pragma unroll
        for (int kt = 0; kt < 5; ++kt) {
            const int r0 = 32 * wrow + 16 * mt + qid;
            const int k0 = 16 * kt + 2 * tig;
            #pragma unroll
            for (int rr = 0; rr < 4; ++rr) {          // a0..a3
                const int g = r0 + ((rr & 1) ? 8 : 0);
                const int k = k0 + ((rr & 2) ? 8 : 0);
                float v0 = 0.f, v1 = 0.f;
                #pragma unroll
                for (int e = 0; e < 2; ++e) {
                    const int kk = k + e;
                    float v = 0.f;
                    if (kk < 64)       v = w_hh[g * HID + kk];
                    else if (kk == 64) v = w_ih[g];
                    else if (kk == 65) v = b_ih[g] + b_hh[g];
                    if (e == 0) v0 = v; else v1 = v;
                }
                split2(v0, v1, whi[mt][kt][rr], wlo[mt][kt][rr]);
            }
        }
    }

    // ---- init H = 0; x chunk 0; k=64/65 slots for t=0 ----
    for (int i = tid; i < NB * HSTRIDE; i += THREADS) { Hhi[i] = 0u; Hlo[i] = 0u; }
    for (int i = tid; i < NB * 64; i += THREADS) {
        int b = i >> 6, s = i & 63;
        x_sh[0][b][s] = x[(size_t)(b0 + b) * T_LEN + s];
    }
    __syncthreads();
    if (tid < NB) {
        float xv = x_sh[0][tid][0];
        uint32_t hi, lo;
        split2(xv, 1.0f, hi, lo);
        lo &= 0xFFFFu;                         // bias lo = 0 exactly
        Hhi[tid * HSTRIDE + 32] = hi;
        Hlo[tid * HSTRIDE + 32] = lo;
    }

    // ---- update identity: warp = batch wid, units lane and lane+32 ----
    const float wfc0 = w_fc[lane], wfc1 = w_fc[lane + 32];
    const float bfc  = b_fc[0];
    float c0 = 0.f, c1 = 0.f;

    __syncthreads();

    for (int t = 0; t < T_LEN; ++t) {
        // ---- MMA phase: 3 independent accumulator chains (depth 5 each) ----
        float a0[2][4], a1[2][4], a2[2][4];
        #pragma unroll
        for (int mt = 0; mt < 2; ++mt)
            #pragma unroll
            for (int i = 0; i < 4; ++i) { a0[mt][i] = 0.f; a1[mt][i] = 0.f; a2[mt][i] = 0.f; }

        #pragma unroll
        for (int kt = 0; kt < 5; ++kt) {
            const int base = (8 * bh8 + qid) * HSTRIDE + 8 * kt + tig;
            uint32_t bhv0 = Hhi[base], bhv1 = Hhi[base + 4];
            uint32_t blv0 = Hlo[base], blv1 = Hlo[base + 4];
            #pragma unroll
            for (int mt = 0; mt < 2; ++mt) {
                MMA_BF16(a0[mt], whi[mt][kt], bhv0, bhv1);   // Whi*Hhi
                MMA_BF16(a1[mt], whi[mt][kt], blv0, blv1);   // Whi*Hlo
                MMA_BF16(a2[mt], wlo[mt][kt], bhv0, bhv1);   // Wlo*Hhi
            }
        }

        // ---- scatter gates to gbuf[b][g] (bank-verified conflict-free) ----
        #pragma unroll
        for (int mt = 0; mt < 2; ++mt) {
            const int g = 32 * wrow + 16 * mt + qid;
            const int b = 8 * bh8 + 2 * tig;
            float v0 = a0[mt][0] + a1[mt][0] + a2[mt][0];
            float v1 = a0[mt][1] + a1[mt][1] + a2[mt][1];
            float v2 = a0[mt][2] + a1[mt][2] + a2[mt][2];
            float v3 = a0[mt][3] + a1[mt][3] + a2[mt][3];
            gbuf[b * GP + g]           = v0;
            gbuf[(b + 1) * GP + g]     = v1;
            gbuf[b * GP + g + 8]       = v2;
            gbuf[(b + 1) * GP + g + 8] = v3;
        }
        __syncthreads();                        // bar1: gates visible

        // ---- update: warp = batch `wid`, units lane & lane+32 ----
        // PyTorch gate order i,f,g,o at row offsets 0,64,128,192
        const float* gb = gbuf + wid * GP;
        float gi0 = gb[lane],       gf0 = gb[lane + 64];
        float gg0 = gb[lane + 128], go0 = gb[lane + 192];
        float gi1 = gb[lane + 32],  gf1 = gb[lane + 96];
        float gg1 = gb[lane + 160], go1 = gb[lane + 224];

        float iv0 = sigm(gi0), fv0 = sigm(gf0);
        float gv0 = tanh_mufu(gg0), ov0 = sigm(go0);
        c0 = fmaf(fv0, c0, iv0 * gv0);
        float hv0 = ov0 * tanh_mufu(c0);

        float iv1 = sigm(gi1), fv1 = sigm(gf1);
        float gv1 = tanh_mufu(gg1), ov1 = sigm(go1);
        c1 = fmaf(fv1, c1, iv1 * gv1);
        float hv1 = ov1 * tanh_mufu(c1);

        // H write (warp wid owns batch row wid)
        __nv_bfloat16 h0h = __float2bfloat16(hv0);
        __nv_bfloat16 h1h = __float2bfloat16(hv1);
        ((__nv_bfloat16*)Hhi)[wid * (2 * HSTRIDE) + lane]      = h0h;
        ((__nv_bfloat16*)Hhi)[wid * (2 * HSTRIDE) + lane + 32] = h1h;
        ((__nv_bfloat16*)Hlo)[wid * (2 * HSTRIDE) + lane] =
            __float2bfloat16(hv0 - __bfloat162float(h0h));
        ((__nv_bfloat16*)Hlo)[wid * (2 * HSTRIDE) + lane + 32] =
            __float2bfloat16(hv1 - __bfloat162float(h1h));

        // output head: full intra-warp reduce, direct store (no extra barrier)
        float po = fmaf(hv0, wfc0, hv1 * wfc1);
        #pragma unroll
        for (int off = 16; off > 0; off >>= 1)
            po += __shfl_xor_sync(0xffffffffu, po, off);
        if (lane == 0) out[(size_t)(b0 + wid) * T_LEN + t] = po + bfc;

        // x/bias slot for step t+1
        if (tid < NB && t + 1 < T_LEN) {
            const int tn = t + 1;
            float xv = x_sh[(tn >> 6) & 1][tid][tn & 63];
            uint32_t hi, lo;
            split2(xv, 1.0f, hi, lo);
            lo &= 0xFFFFu;
            Hhi[tid * HSTRIDE + 32] = hi;
            Hlo[tid * HSTRIDE + 32] = lo;
        }
        // stage next 64-step x chunk at chunk start
        if ((t & 63) == 0 && (t >> 6) + 1 < T_LEN / 64) {
            const int nc = (t >> 6) + 1;
            #pragma unroll
            for (int q = 0; q < 2; ++q) {
                int idx = tid + THREADS * q;
                int b = idx >> 6, s = idx & 63;
                x_sh[nc & 1][b][s] = x[(size_t)(b0 + b) * T_LEN + nc * 64 + s];
            }
        }
        __syncthreads();                        // bar2: H visible for next step
    }
}

extern "C" void kernel_launch(void* const* d_in, const int* in_sizes, int n_in,
                              void* d_out, int out_size)
{
    const float* x    = (const float*)d_in[0];
    const float* w_ih = (const float*)d_in[1];
    const float* w_hh = (const float*)d_in[2];
    const float* b_ih = (const float*)d_in[3];
    const float* b_hh = (const float*)d_in[4];
    const float* w_fc = (const float*)d_in[5];
    const float* b_fc = (const float*)d_in[6];
    float* out = (float*)d_out;

    lstm_kernel<<<BATCH / NB, THREADS>>>(x, w_ih, w_hh, b_ih, b_hh,
                                         w_fc, b_fc, out);
}

// round 11
// speedup vs baseline: 3.2728x; 1.2377x over previous
#include <cuda_runtime.h>
#include <cuda_bf16.h>
#include <cstdint>

#define T_LEN   512
#define BATCH   2048
#define NB      16            // batches per CTA
#define HID     64
#define THREADS 512           // 16 warps: (w&7) = 32-row slice, (w>>3) = batch half
#define HSTRIDE 44            // u32 words per batch row of H (bank-verified)
#define GP      260           // floats per batch row of gbuf (bank-verified)

#define HALF_BAR(h)                                                           \
    asm volatile("bar.sync %0, %1;" :: "r"(1 + (h)), "r"(256) : "memory")

static __device__ __forceinline__ float tanh_mufu(float x) {
    float r; asm("tanh.approx.f32 %0, %1;" : "=f"(r) : "f"(x)); return r;
}
static __device__ __forceinline__ float sigm(float x) {
    return fmaf(tanh_mufu(0.5f * x), 0.5f, 0.5f);
}
static __device__ __forceinline__ uint32_t pk2(__nv_bfloat16 a, __nv_bfloat16 b) {
    return ((uint32_t)__bfloat16_as_ushort(b) << 16) | (uint32_t)__bfloat16_as_ushort(a);
}
// split (a,b) into packed hi and lo bf16x2 words (low half = first element)
static __device__ __forceinline__ void split2(float a, float b,
                                              uint32_t& hi, uint32_t& lo) {
    __nv_bfloat16 ah = __float2bfloat16(a), bh = __float2bfloat16(b);
    __nv_bfloat16 al = __float2bfloat16(a - __bfloat162float(ah));
    __nv_bfloat16 bl = __float2bfloat16(b - __bfloat162float(bh));
    hi = pk2(ah, bh); lo = pk2(al, bl);
}

// Ampere-class HMMA: m16n8k16, A row-major bf16, B col-major bf16, f32 accum
#define MMA_BF16(d, a, b0v, b1v)                                              \
    asm volatile("mma.sync.aligned.m16n8k16.row.col.f32.bf16.bf16.f32 "        \
        "{%0,%1,%2,%3}, {%4,%5,%6,%7}, {%8,%9}, {%0,%1,%2,%3};"                \
        : "+f"((d)[0]), "+f"((d)[1]), "+f"((d)[2]), "+f"((d)[3])               \
        : "r"((a)[0]), "r"((a)[1]), "r"((a)[2]), "r"((a)[3]),                  \
          "r"(b0v), "r"(b1v))

__global__ __launch_bounds__(THREADS, 1)
void lstm_kernel(const float* __restrict__ x,
                 const float* __restrict__ w_ih,
                 const float* __restrict__ w_hh,
                 const float* __restrict__ b_ih,
                 const float* __restrict__ b_hh,
                 const float* __restrict__ w_fc,
                 const float* __restrict__ b_fc,
                 float* __restrict__ out)
{
    __shared__ uint32_t Hhi[NB * HSTRIDE];   // bf16x2 words: [b][k/2]
    __shared__ uint32_t Hlo[NB * HSTRIDE];
    __shared__ float    gbuf[NB * GP];       // [b][gate row]
    __shared__ float    x_sh[2][NB][64];

    const int tid  = threadIdx.x;
    const int lane = tid & 31;
    const int wid  = tid >> 5;
    const int wrow = wid & 7;                 // row-slice warp id
    const int bh8  = wid >> 3;                // batch half (0: b 0-7, 1: b 8-15)
    const int qid  = lane >> 2;               // fragment groupID
    const int tig  = lane & 3;                // thread-in-group
    const int b0   = blockIdx.x * NB;

    // ---- build resident W_aug fragments (hi/lo split), rows = gate index ----
    // K layout: k<64 = w_hh, k=64 = w_ih (I==1), k=65 = b_ih+b_hh, else 0
    uint32_t whi[2][5][4], wlo[2][5][4];
    #pragma unroll
    for (int mt = 0; mt < 2; ++mt) {
        #pragma unroll
        for (int kt = 0; kt < 5; ++kt) {
            const int r0 = 32 * wrow + 16 * mt + qid;
            const int k0 = 16 * kt + 2 * tig;
            #pragma unroll
            for (int rr = 0; rr < 4; ++rr) {          // a0..a3
                const int g = r0 + ((rr & 1) ? 8 : 0);
                const int k = k0 + ((rr & 2) ? 8 : 0);
                float v0 = 0.f, v1 = 0.f;
                #pragma unroll
                for (int e = 0; e < 2; ++e) {
                    const int kk = k + e;
                    float v = 0.f;
                    if (kk < 64)       v = w_hh[g * HID + kk];
                    else if (kk == 64) v = w_ih[g];
                    else if (kk == 65) v = b_ih[g] + b_hh[g];
                    if (e == 0) v0 = v; else v1 = v;
                }
                split2(v0, v1, whi[mt][kt][rr], wlo[mt][kt][rr]);
            }
        }
    }

    // ---- init H = 0; x chunk 0; k=64/65 slots for t=0 ----
    for (int i = tid; i < NB * HSTRIDE; i += THREADS) { Hhi[i] = 0u; Hlo[i] = 0u; }
    for (int i = tid; i < NB * 64; i += THREADS) {
        int b = i >> 6, s = i & 63;
        x_sh[0][b][s] = x[(size_t)(b0 + b) * T_LEN + s];
    }
    __syncthreads();
    if (tid < NB) {
        float xv = x_sh[0][tid][0];
        uint32_t hi, lo;
        split2(xv, 1.0f, hi, lo);
        lo &= 0xFFFFu;                         // bias lo = 0 exactly
        Hhi[tid * HSTRIDE + 32] = hi;
        Hlo[tid * HSTRIDE + 32] = lo;
    }

    // ---- update identity: warp = batch wid, units lane and lane+32 ----
    const float wfc0 = w_fc[lane], wfc1 = w_fc[lane + 32];
    const float bfc  = b_fc[0];
    float c0 = 0.f, c1 = 0.f;
    float po_pend = 0.f;                       // deferred output partial

    __syncthreads();

    for (int t = 0; t < T_LEN; ++t) {
        // ---- deferred output head for step t-1 (overlaps next MMA issue) ----
        if (t > 0) {
            float po = po_pend;
            #pragma unroll
            for (int off = 16; off > 0; off >>= 1)
                po += __shfl_xor_sync(0xffffffffu, po, off);
            if (lane == 0) out[(size_t)(b0 + wid) * T_LEN + (t - 1)] = po + bfc;
        }

        // ---- MMA phase: 3 independent accumulator chains (depth 5 each) ----
        float a0[2][4], a1[2][4], a2[2][4];
        #pragma unroll
        for (int mt = 0; mt < 2; ++mt)
            #pragma unroll
            for (int i = 0; i < 4; ++i) { a0[mt][i] = 0.f; a1[mt][i] = 0.f; a2[mt][i] = 0.f; }

        #pragma unroll
        for (int kt = 0; kt < 5; ++kt) {
            const int base = (8 * bh8 + qid) * HSTRIDE + 8 * kt + tig;
            uint32_t bhv0 = Hhi[base], bhv1 = Hhi[base + 4];
            uint32_t blv0 = Hlo[base], blv1 = Hlo[base + 4];
            #pragma unroll
            for (int mt = 0; mt < 2; ++mt) {
                MMA_BF16(a0[mt], whi[mt][kt], bhv0, bhv1);   // Whi*Hhi
                MMA_BF16(a1[mt], whi[mt][kt], blv0, blv1);   // Whi*Hlo
                MMA_BF16(a2[mt], wlo[mt][kt], bhv0, bhv1);   // Wlo*Hhi
            }
        }

        // ---- scatter gates to gbuf[b][g] (bank-verified conflict-free) ----
        #pragma unroll
        for (int mt = 0; mt < 2; ++mt) {
            const int g = 32 * wrow + 16 * mt + qid;
            const int b = 8 * bh8 + 2 * tig;
            gbuf[b * GP + g]           = a0[mt][0] + a1[mt][0] + a2[mt][0];
            gbuf[(b + 1) * GP + g]     = a0[mt][1] + a1[mt][1] + a2[mt][1];
            gbuf[b * GP + g + 8]       = a0[mt][2] + a1[mt][2] + a2[mt][2];
            gbuf[(b + 1) * GP + g + 8] = a0[mt][3] + a1[mt][3] + a2[mt][3];
        }
        HALF_BAR(bh8);                          // bar1: this half's gates visible

        // ---- update: warp = batch `wid`, units lane & lane+32 ----
        // PyTorch gate order i,f,g,o at row offsets 0,64,128,192
        const float* gb = gbuf + wid * GP;
        float gi0 = gb[lane],       gf0 = gb[lane + 64];
        float gg0 = gb[lane + 128], go0 = gb[lane + 192];
        float gi1 = gb[lane + 32],  gf1 = gb[lane + 96];
        float gg1 = gb[lane + 160], go1 = gb[lane + 224];

        float iv0 = sigm(gi0), fv0 = sigm(gf0);
        float gv0 = tanh_mufu(gg0), ov0 = sigm(go0);
        c0 = fmaf(fv0, c0, iv0 * gv0);
        float hv0 = ov0 * tanh_mufu(c0);

        float iv1 = sigm(gi1), fv1 = sigm(gf1);
        float gv1 = tanh_mufu(gg1), ov1 = sigm(go1);
        c1 = fmaf(fv1, c1, iv1 * gv1);
        float hv1 = ov1 * tanh_mufu(c1);

        // H write (warp wid owns batch row wid)
        __nv_bfloat16 h0h = __float2bfloat16(hv0);
        __nv_bfloat16 h1h = __float2bfloat16(hv1);
        ((__nv_bfloat16*)Hhi)[wid * (2 * HSTRIDE) + lane]      = h0h;
        ((__nv_bfloat16*)Hhi)[wid * (2 * HSTRIDE) + lane + 32] = h1h;
        ((__nv_bfloat16*)Hlo)[wid * (2 * HSTRIDE) + lane] =
            __float2bfloat16(hv0 - __bfloat162float(h0h));
        ((__nv_bfloat16*)Hlo)[wid * (2 * HSTRIDE) + lane + 32] =
            __float2bfloat16(hv1 - __bfloat162float(h1h));

        // output partial, reduced after the barrier (next iteration)
        po_pend = fmaf(hv0, wfc0, hv1 * wfc1);

        // x/bias slot for step t+1 (half-local: first warp of half, lanes 0-7)
        if (wrow == 0 && lane < 8 && t + 1 < T_LEN) {
            const int tn = t + 1;
            const int b = 8 * bh8 + lane;
            float xv = x_sh[(tn >> 6) & 1][b][tn & 63];
            uint32_t hi, lo;
            split2(xv, 1.0f, hi, lo);
            lo &= 0xFFFFu;
            Hhi[b * HSTRIDE + 32] = hi;
            Hlo[b * HSTRIDE + 32] = lo;
        }
        // stage next 64-step x chunk at chunk start (half-local)
        if ((t & 63) == 0 && (t >> 6) + 1 < T_LEN / 64) {
            const int nc = (t >> 6) + 1;
            const int lt = tid & 255;
            #pragma unroll
            for (int q = 0; q < 2; ++q) {
                int idx = lt + 256 * q;                  // 0..511
                int b = 8 * bh8 + (idx >> 6);
                int s = idx & 63;
                x_sh[nc & 1][b][s] = x[(size_t)(b0 + b) * T_LEN + nc * 64 + s];
            }
        }
        HALF_BAR(bh8);                          // bar2: this half's H visible
    }

    // final deferred output (t = T_LEN-1)
    {
        float po = po_pend;
        #pragma unroll
        for (int off = 16; off > 0; off >>= 1)
            po += __shfl_xor_sync(0xffffffffu, po, off);
        if (lane == 0) out[(size_t)(b0 + wid) * T_LEN + (T_LEN - 1)] = po + bfc;
    }
}

extern "C" void kernel_launch(void* const* d_in, const int* in_sizes, int n_in,
                              void* d_out, int out_size)
{
    const float* x    = (const float*)d_in[0];
    const float* w_ih = (const float*)d_in[1];
    const float* w_hh = (const float*)d_in[2];
    const float* b_ih = (const float*)d_in[3];
    const float* b_hh = (const float*)d_in[4];
    const float* w_fc = (const float*)d_in[5];
    const float* b_fc = (const float*)d_in[6];
    float* out = (float*)d_out;

    lstm_kernel<<<BATCH / NB, THREADS>>>(x, w_ih, w_hh, b_ih, b_hh,
                                         w_fc, b_fc, out);
}